// round 3
// baseline (speedup 1.0000x reference)
#include <cuda_runtime.h>
#include <math.h>

// ---------------- problem constants ----------------
#define D_MODEL  2048
#define N_HEADS  16
#define HEAD_DIM 128
#define BATCH    2
#define SEQ      2048
#define M_TOT    (BATCH * SEQ)      // 4096 rows for all GEMMs

// ---------------- scratch (alloc-free rule: __device__ globals) ----------------
__device__ float g_Q[M_TOT * D_MODEL];
__device__ float g_K[M_TOT * D_MODEL];
__device__ float g_V[M_TOT * D_MODEL];
__device__ float g_C[M_TOT * D_MODEL];

// ============================================================================
// SGEMM: C[m,n] = sum_k A[m*K+k] * B[n*K+k]   (both K-contiguous, row-major)
// Matches einsum 'bse,fe->bsf' (A=x, B=W) and 'bsf,ef->bse' (A=ctx, B=Wo).
// 128x128 tile, K-step 8, 256 threads, 8x8 microtile per thread.
// ============================================================================
__global__ __launch_bounds__(256) void sgemm_nt(const float* __restrict__ A,
                                                const float* __restrict__ B,
                                                float* __restrict__ C,
                                                int M, int N, int K)
{
    __shared__ float As[8][128];
    __shared__ float Bs[8][128];

    const int tid = threadIdx.x;
    const int tx  = tid & 15;        // 0..15 -> N direction
    const int ty  = tid >> 4;        // 0..15 -> M direction
    const int bm  = blockIdx.y * 128;
    const int bn  = blockIdx.x * 128;

    // global load mapping: 128 rows x 8 k-floats per tile; each thread loads one float4
    const int lr = tid >> 1;         // 0..127
    const int lc = (tid & 1) * 4;    // 0 or 4

    const float* Ap = A + (size_t)(bm + lr) * K + lc;
    const float* Bp = B + (size_t)(bn + lr) * K + lc;

    float acc[8][8];
#pragma unroll
    for (int i = 0; i < 8; i++)
#pragma unroll
        for (int j = 0; j < 8; j++) acc[i][j] = 0.f;

    for (int k0 = 0; k0 < K; k0 += 8) {
        float4 av = *(const float4*)(Ap + k0);
        float4 bv = *(const float4*)(Bp + k0);
        As[lc + 0][lr] = av.x; As[lc + 1][lr] = av.y;
        As[lc + 2][lr] = av.z; As[lc + 3][lr] = av.w;
        Bs[lc + 0][lr] = bv.x; Bs[lc + 1][lr] = bv.y;
        Bs[lc + 2][lr] = bv.z; Bs[lc + 3][lr] = bv.w;
        __syncthreads();

#pragma unroll
        for (int kk = 0; kk < 8; kk++) {
            float a[8], b[8];
            *(float4*)(a)     = *(const float4*)&As[kk][ty * 8];
            *(float4*)(a + 4) = *(const float4*)&As[kk][ty * 8 + 4];
            *(float4*)(b)     = *(const float4*)&Bs[kk][tx * 8];
            *(float4*)(b + 4) = *(const float4*)&Bs[kk][tx * 8 + 4];
#pragma unroll
            for (int i = 0; i < 8; i++)
#pragma unroll
                for (int j = 0; j < 8; j++)
                    acc[i][j] = fmaf(a[i], b[j], acc[i][j]);
        }
        __syncthreads();
    }

#pragma unroll
    for (int i = 0; i < 8; i++) {
        float* cp = C + (size_t)(bm + ty * 8 + i) * N + bn + tx * 8;
        *(float4*)(cp)     = *(const float4*)&acc[i][0];
        *(float4*)(cp + 4) = *(const float4*)&acc[i][4];
    }
}

// ============================================================================
// RoPE applied in-place to Q and K (layout [b, s, h*d]).
// pair i in [0,64): even=2i, odd=2i+1; ang = pos * theta^(-2i/128)
// ============================================================================
__global__ void rope_kernel(float* __restrict__ Q, float* __restrict__ K,
                            const int* __restrict__ pos)
{
    int idx = blockIdx.x * blockDim.x + threadIdx.x;
    const int total = BATCH * SEQ * N_HEADS * (HEAD_DIM / 2);
    if (idx >= total) return;

    int i  = idx & 63;                       // pair index 0..63
    int h  = (idx >> 6) & (N_HEADS - 1);
    int ss = (idx >> 10) & (SEQ - 1);
    int b  = idx >> 21;

    int p = pos[b * SEQ + ss];
    float inv_freq = powf(10000.0f, -(2.0f * (float)i) / 128.0f);
    float ang = (float)p * inv_freq;
    float s, c;
    sincosf(ang, &s, &c);

    size_t base = ((size_t)(b * SEQ + ss)) * D_MODEL + h * HEAD_DIM + 2 * i;
    float qe = Q[base], qo = Q[base + 1];
    Q[base]     = qe * c - qo * s;
    Q[base + 1] = qe * s + qo * c;
    float ke = K[base], ko = K[base + 1];
    K[base]     = ke * c - ko * s;
    K[base + 1] = ke * s + ko * c;
}

// ============================================================================
// Causal flash attention, fp32.
// Grid: (SEQ/BQ, BATCH*N_HEADS). Block: 256 threads = 64 q-rows x 4 parts.
// Each thread owns 32 of the 128 head dims for its row; dot products are
// reduced over the 4-thread quad with shfl.
// ============================================================================
#define BQ 64
#define BK 32

__global__ __launch_bounds__(256) void flash_kernel(const float* __restrict__ Q,
                                                    const float* __restrict__ K,
                                                    const float* __restrict__ V,
                                                    float* __restrict__ O)
{
    __shared__ float Ks[BK][HEAD_DIM];
    __shared__ float Vs[BK][HEAD_DIM];
    __shared__ float Ps[BQ][BK];

    const int bh = blockIdx.y;
    const int b  = bh / N_HEADS;
    const int h  = bh % N_HEADS;
    const int q0 = blockIdx.x * BQ;

    const int tid  = threadIdx.x;
    const int row  = tid >> 2;     // 0..63
    const int part = tid & 3;      // 0..3
    const int qg   = q0 + row;

    const float scale = 0.08838834764831845f;   // 1/sqrt(128)

    // q fragment: 32 dims starting at part*32
    float qf[32];
    const float* qp = Q + ((size_t)(b * SEQ + qg)) * D_MODEL + h * HEAD_DIM + part * 32;
#pragma unroll
    for (int i = 0; i < 32; i += 4)
        *(float4*)(qf + i) = *(const float4*)(qp + i);

    float acc[32];
#pragma unroll
    for (int i = 0; i < 32; i++) acc[i] = 0.f;
    float m = -1e30f, l = 0.f;

    const int kend = q0 + BQ;      // causal: no k-block beyond the diagonal
    for (int k0 = 0; k0 < kend; k0 += BK) {
        __syncthreads();           // prior-iteration smem consumers done
        // cooperative load of K/V tiles (BK x 128 floats each)
        {
            const size_t rbase = (size_t)(b * SEQ + k0) * D_MODEL + h * HEAD_DIM;
            for (int idx = tid; idx < BK * (HEAD_DIM / 4); idx += 256) {
                int r = idx >> 5;            // 0..BK-1
                int c = (idx & 31) * 4;      // 0..124
                ((float4*)Ks)[idx] = *(const float4*)(K + rbase + (size_t)r * D_MODEL + c);
                ((float4*)Vs)[idx] = *(const float4*)(V + rbase + (size_t)r * D_MODEL + c);
            }
        }
        __syncthreads();

        // scores for BK keys; each quad computes the full 128-dot via shfl
        float sv[BK / 4];
        float mblk = -1e30f;
#pragma unroll
        for (int j = 0; j < BK; j++) {
            const float* kr = &Ks[j][part * 32];
            float d = 0.f;
#pragma unroll
            for (int i = 0; i < 32; i++) d = fmaf(qf[i], kr[i], d);
            d += __shfl_xor_sync(0xffffffffu, d, 1);
            d += __shfl_xor_sync(0xffffffffu, d, 2);
            d *= scale;
            int kg = k0 + j;
            d = (kg <= qg) ? d : -1e30f;
            if ((j & 3) == part) sv[j >> 2] = d;
            mblk = fmaxf(mblk, d);
        }

        float mnew  = fmaxf(m, mblk);
        float alpha = __expf(m - mnew);
        float ladd  = 0.f;
#pragma unroll
        for (int jj = 0; jj < BK / 4; jj++) {
            float p = __expf(sv[jj] - mnew);
            ladd += p;
            Ps[row][jj * 4 + part] = p;
        }
        ladd += __shfl_xor_sync(0xffffffffu, ladd, 1);
        ladd += __shfl_xor_sync(0xffffffffu, ladd, 2);
        l = l * alpha + ladd;
        m = mnew;
#pragma unroll
        for (int i = 0; i < 32; i++) acc[i] *= alpha;
        __syncwarp();              // Ps[row][*] written within this warp's quads

        // PV accumulate
#pragma unroll 4
        for (int j = 0; j < BK; j++) {
            float p = Ps[row][j];
            const float* vr = &Vs[j][part * 32];
#pragma unroll
            for (int i = 0; i < 32; i++) acc[i] = fmaf(p, vr[i], acc[i]);
        }
    }

    float inv_l = 1.0f / l;
    float* op = O + ((size_t)(b * SEQ + qg)) * D_MODEL + h * HEAD_DIM + part * 32;
#pragma unroll
    for (int i = 0; i < 32; i++) op[i] = acc[i] * inv_l;
}

// ============================================================================
// launch
// ============================================================================
extern "C" void kernel_launch(void* const* d_in, const int* in_sizes, int n_in,
                              void* d_out, int out_size)
{
    const float* x   = (const float*)d_in[0];
    const int*   pos = (const int*)  d_in[1];
    const float* Wq  = (const float*)d_in[2];
    const float* Wk  = (const float*)d_in[3];
    const float* Wv  = (const float*)d_in[4];
    const float* Wo  = (const float*)d_in[5];
    float* out = (float*)d_out;

    float *Qb, *Kb, *Vb, *Cb;
    cudaGetSymbolAddress((void**)&Qb, g_Q);
    cudaGetSymbolAddress((void**)&Kb, g_K);
    cudaGetSymbolAddress((void**)&Vb, g_V);
    cudaGetSymbolAddress((void**)&Cb, g_C);

    dim3 gemmGrid(D_MODEL / 128, M_TOT / 128);   // (16, 32)
    sgemm_nt<<<gemmGrid, 256>>>(x, Wq, Qb, M_TOT, D_MODEL, D_MODEL);
    sgemm_nt<<<gemmGrid, 256>>>(x, Wk, Kb, M_TOT, D_MODEL, D_MODEL);
    sgemm_nt<<<gemmGrid, 256>>>(x, Wv, Vb, M_TOT, D_MODEL, D_MODEL);

    int ropeTotal = BATCH * SEQ * N_HEADS * (HEAD_DIM / 2);
    rope_kernel<<<(ropeTotal + 255) / 256, 256>>>(Qb, Kb, pos);

    dim3 flashGrid(SEQ / BQ, BATCH * N_HEADS);   // (32, 32)
    flash_kernel<<<flashGrid, 256>>>(Qb, Kb, Vb, Cb);

    sgemm_nt<<<gemmGrid, 256>>>(Cb, Wo, out, M_TOT, D_MODEL, D_MODEL);
}

// round 5
// speedup vs baseline: 2.0305x; 2.0305x over previous
#include <cuda_runtime.h>
#include <cuda_bf16.h>
#include <cstdint>
#include <math.h>

// ---------------- problem constants ----------------
#define D_MODEL  2048
#define N_HEADS  16
#define HEAD_DIM 128
#define BATCH    2
#define SEQ      2048
#define M_TOT    (BATCH * SEQ)      // 4096 rows for activation GEMMs

// ---------------- scratch (alloc-free rule: __device__ globals) ----------------
__device__ float g_Q[M_TOT * D_MODEL];
__device__ float g_K[M_TOT * D_MODEL];
__device__ float g_V[M_TOT * D_MODEL];
__device__ float g_C[M_TOT * D_MODEL];

// bf16 split (hi/lo) operands
__device__ __nv_bfloat16 g_xh[M_TOT * D_MODEL];
__device__ __nv_bfloat16 g_xl[M_TOT * D_MODEL];
__device__ __nv_bfloat16 g_ch[M_TOT * D_MODEL];
__device__ __nv_bfloat16 g_cl[M_TOT * D_MODEL];
__device__ __nv_bfloat16 g_Wh[4 * D_MODEL * D_MODEL];   // Wq,Wk,Wv,Wo slices
__device__ __nv_bfloat16 g_Wl[4 * D_MODEL * D_MODEL];

// ============================================================================
// PTX helpers (compute_103-safe: mma.sync / ldmatrix / cp.async only)
// ============================================================================
__device__ __forceinline__ uint32_t smem_u32(const void* p) {
    uint32_t a;
    asm("{ .reg .u64 t; cvta.to.shared.u64 t, %1; cvt.u32.u64 %0, t; }" : "=r"(a) : "l"(p));
    return a;
}

__device__ __forceinline__ void ldmatrix_x4(uint32_t* r, uint32_t addr) {
    asm volatile("ldmatrix.sync.aligned.m8n8.x4.shared.b16 {%0,%1,%2,%3}, [%4];"
                 : "=r"(r[0]), "=r"(r[1]), "=r"(r[2]), "=r"(r[3]) : "r"(addr));
}

__device__ __forceinline__ void mma_bf16(float* c, const uint32_t* a, const uint32_t* b) {
    asm volatile(
        "mma.sync.aligned.m16n8k16.row.col.f32.bf16.bf16.f32 "
        "{%0,%1,%2,%3}, {%4,%5,%6,%7}, {%8,%9}, {%0,%1,%2,%3};"
        : "+f"(c[0]), "+f"(c[1]), "+f"(c[2]), "+f"(c[3])
        : "r"(a[0]), "r"(a[1]), "r"(a[2]), "r"(a[3]), "r"(b[0]), "r"(b[1]));
}

__device__ __forceinline__ void cp16(uint32_t s, const void* g) {
    asm volatile("cp.async.cg.shared.global [%0], [%1], 16;" :: "r"(s), "l"(g));
}
__device__ __forceinline__ void cp_commit() {
    asm volatile("cp.async.commit_group;" ::: "memory");
}
__device__ __forceinline__ void cp_wait1() {
    asm volatile("cp.async.wait_group 1;" ::: "memory");
}

// ============================================================================
// fp32 -> bf16 hi/lo split conversion (vectorized)
// ============================================================================
__global__ void cvt_kernel(const float* __restrict__ in,
                           __nv_bfloat16* __restrict__ hi,
                           __nv_bfloat16* __restrict__ lo, int n4)
{
    int i = blockIdx.x * blockDim.x + threadIdx.x;
    if (i >= n4) return;
    float4 v = ((const float4*)in)[i];
    __nv_bfloat16 h0 = __float2bfloat16(v.x), h1 = __float2bfloat16(v.y);
    __nv_bfloat16 h2 = __float2bfloat16(v.z), h3 = __float2bfloat16(v.w);
    __nv_bfloat16 l0 = __float2bfloat16(v.x - __bfloat162float(h0));
    __nv_bfloat16 l1 = __float2bfloat16(v.y - __bfloat162float(h1));
    __nv_bfloat16 l2 = __float2bfloat16(v.z - __bfloat162float(h2));
    __nv_bfloat16 l3 = __float2bfloat16(v.w - __bfloat162float(h3));
    __nv_bfloat162* hp = (__nv_bfloat162*)hi;
    __nv_bfloat162* lp = (__nv_bfloat162*)lo;
    __nv_bfloat162 a; a.x = h0; a.y = h1; hp[2*i] = a;
    __nv_bfloat162 b; b.x = h2; b.y = h3; hp[2*i+1] = b;
    __nv_bfloat162 c; c.x = l0; c.y = l1; lp[2*i] = c;
    __nv_bfloat162 d; d.x = l2; d.y = l3; lp[2*i+1] = d;
}

// ============================================================================
// bf16x3 GEMM via mma.sync: C[m,n] = sum_k A[m,k]*B[n,k]
//   AhBh + AhBl + AlBh, fp32 accumulation.
// CTA 128x128, BK=32, 256 threads (8 warps, warp tile 64x32), 2-stage cp.async.
// SMEM tile layout: [128 rows][4 x 16B chunks], chunk XOR-swizzled by (row>>1)&3.
// ============================================================================
#define BK        32
#define NITER     (D_MODEL / BK)          // 64
#define TILE_B2   8192                    // 128 rows * 64B
#define STAGE_B2  (4 * TILE_B2)           // Ah, Al, Bh, Bl
#define SMEM_GEMM (2 * STAGE_B2)          // 64 KB

__device__ __forceinline__ uint32_t sw_addr(uint32_t tile_base, int row, int chunk) {
    return tile_base + row * 64 + ((chunk ^ ((row >> 1) & 3)) << 4);
}

__device__ __forceinline__ void issue_stage(
    uint32_t stage_base,
    const __nv_bfloat16* __restrict__ Ah, const __nv_bfloat16* __restrict__ Al,
    const __nv_bfloat16* __restrict__ Bh, const __nv_bfloat16* __restrict__ Bl,
    int bm, int bn, int k0, int tid)
{
#pragma unroll
    for (int j = 0; j < 2; j++) {
        int idx = tid + 256 * j;            // 0..511
        int row = idx >> 2;                 // 0..127
        int ch  = idx & 3;                  // 16B chunk
        uint32_t soff = (uint32_t)(row * 64 + ((ch ^ ((row >> 1) & 3)) << 4));
        size_t ga = (size_t)(bm + row) * D_MODEL + k0 + ch * 8;
        size_t gb = (size_t)(bn + row) * D_MODEL + k0 + ch * 8;
        cp16(stage_base + 0 * TILE_B2 + soff, Ah + ga);
        cp16(stage_base + 1 * TILE_B2 + soff, Al + ga);
        cp16(stage_base + 2 * TILE_B2 + soff, Bh + gb);
        cp16(stage_base + 3 * TILE_B2 + soff, Bl + gb);
    }
}

__global__ void __launch_bounds__(256) mma_gemm_kernel(
    const __nv_bfloat16* __restrict__ Ah, const __nv_bfloat16* __restrict__ Al,
    const __nv_bfloat16* __restrict__ Bh, const __nv_bfloat16* __restrict__ Bl,
    float* __restrict__ C)
{
    extern __shared__ char sm_raw[];
    const uint32_t sbase = smem_u32(sm_raw);

    const int tid  = threadIdx.x;
    const int lane = tid & 31;
    const int w    = tid >> 5;
    const int wm   = (w & 1) * 64;      // warp m offset in CTA tile
    const int wn   = (w >> 1) * 32;     // warp n offset
    const int bm   = blockIdx.y * 128;
    const int bn   = blockIdx.x * 128;

    // ldmatrix lane addressing
    const int g  = lane >> 3;           // 0..3 (8x8 matrix index)
    const int li = lane & 7;
    const int aRowL = li + ((g & 1) << 3);      // + wm + mi*16
    const int aChL  = g >> 1;                   // + 2*ks
    const int bRowL = li + ((g >> 1) << 3);     // + wn + p*16
    const int bChL  = g & 1;                    // + 2*ks

    float acc[4][4][4];
#pragma unroll
    for (int mi = 0; mi < 4; mi++)
#pragma unroll
        for (int ni = 0; ni < 4; ni++)
#pragma unroll
            for (int r = 0; r < 4; r++) acc[mi][ni][r] = 0.f;

    // prologue: stage 0 (k0=0), stage 1 (k0=BK)
    issue_stage(sbase, Ah, Al, Bh, Bl, bm, bn, 0, tid);
    cp_commit();
    issue_stage(sbase + STAGE_B2, Ah, Al, Bh, Bl, bm, bn, BK, tid);
    cp_commit();

    for (int c = 0; c < NITER; c++) {
        cp_wait1();
        __syncthreads();
        const uint32_t st   = sbase + (uint32_t)(c & 1) * STAGE_B2;
        const uint32_t tAh  = st + 0 * TILE_B2;
        const uint32_t tAl  = st + 1 * TILE_B2;
        const uint32_t tBh  = st + 2 * TILE_B2;
        const uint32_t tBl  = st + 3 * TILE_B2;

#pragma unroll
        for (int ks = 0; ks < 2; ks++) {
            const int aCh = 2 * ks + aChL;
            const int bCh = 2 * ks + bChL;

            uint32_t ah[4][4], bh[4][2], bl[4][2];
#pragma unroll
            for (int mi = 0; mi < 4; mi++)
                ldmatrix_x4(ah[mi], sw_addr(tAh, wm + mi * 16 + aRowL, aCh));
#pragma unroll
            for (int p = 0; p < 2; p++) {
                uint32_t t4[4];
                ldmatrix_x4(t4, sw_addr(tBh, wn + p * 16 + bRowL, bCh));
                bh[2 * p][0] = t4[0]; bh[2 * p][1] = t4[1];
                bh[2 * p + 1][0] = t4[2]; bh[2 * p + 1][1] = t4[3];
                ldmatrix_x4(t4, sw_addr(tBl, wn + p * 16 + bRowL, bCh));
                bl[2 * p][0] = t4[0]; bl[2 * p][1] = t4[1];
                bl[2 * p + 1][0] = t4[2]; bl[2 * p + 1][1] = t4[3];
            }

#pragma unroll
            for (int mi = 0; mi < 4; mi++)
#pragma unroll
                for (int ni = 0; ni < 4; ni++)
                    mma_bf16(acc[mi][ni], ah[mi], bh[ni]);
#pragma unroll
            for (int mi = 0; mi < 4; mi++)
#pragma unroll
                for (int ni = 0; ni < 4; ni++)
                    mma_bf16(acc[mi][ni], ah[mi], bl[ni]);

            uint32_t al[4][4];
#pragma unroll
            for (int mi = 0; mi < 4; mi++)
                ldmatrix_x4(al[mi], sw_addr(tAl, wm + mi * 16 + aRowL, aCh));
#pragma unroll
            for (int mi = 0; mi < 4; mi++)
#pragma unroll
                for (int ni = 0; ni < 4; ni++)
                    mma_bf16(acc[mi][ni], al[mi], bh[ni]);
        }

        __syncthreads();
        if (c + 2 < NITER)
            issue_stage(sbase + (uint32_t)(c & 1) * STAGE_B2, Ah, Al, Bh, Bl,
                        bm, bn, (c + 2) * BK, tid);
        cp_commit();
    }

    // epilogue: direct float2 stores
    const int gid = lane >> 2;          // 0..7
    const int tig = lane & 3;           // 0..3
#pragma unroll
    for (int mi = 0; mi < 4; mi++) {
#pragma unroll
        for (int ni = 0; ni < 4; ni++) {
            int row = bm + wm + mi * 16 + gid;
            int col = bn + wn + ni * 8 + tig * 2;
            float2 v0 = make_float2(acc[mi][ni][0], acc[mi][ni][1]);
            float2 v1 = make_float2(acc[mi][ni][2], acc[mi][ni][3]);
            *(float2*)(C + (size_t)row * D_MODEL + col) = v0;
            *(float2*)(C + (size_t)(row + 8) * D_MODEL + col) = v1;
        }
    }
}

// ============================================================================
// RoPE applied in-place to Q and K (layout [b, s, h*d]).
// ============================================================================
__global__ void rope_kernel(float* __restrict__ Q, float* __restrict__ K,
                            const int* __restrict__ pos)
{
    int idx = blockIdx.x * blockDim.x + threadIdx.x;
    const int total = BATCH * SEQ * N_HEADS * (HEAD_DIM / 2);
    if (idx >= total) return;

    int i  = idx & 63;
    int h  = (idx >> 6) & (N_HEADS - 1);
    int ss = (idx >> 10) & (SEQ - 1);
    int b  = idx >> 21;

    int p = pos[b * SEQ + ss];
    float inv_freq = powf(10000.0f, -(2.0f * (float)i) / 128.0f);
    float ang = (float)p * inv_freq;
    float s, c;
    sincosf(ang, &s, &c);

    size_t base = ((size_t)(b * SEQ + ss)) * D_MODEL + h * HEAD_DIM + 2 * i;
    float qe = Q[base], qo = Q[base + 1];
    Q[base]     = qe * c - qo * s;
    Q[base + 1] = qe * s + qo * c;
    float ke = K[base], ko = K[base + 1];
    K[base]     = ke * c - ko * s;
    K[base + 1] = ke * s + ko * c;
}

// ============================================================================
// Causal flash attention, fp32 (unchanged from passing R3 kernel).
// ============================================================================
#define BQ 64
#define BKF 32

__global__ __launch_bounds__(256) void flash_kernel(const float* __restrict__ Q,
                                                    const float* __restrict__ K,
                                                    const float* __restrict__ V,
                                                    float* __restrict__ O)
{
    __shared__ float Ks[BKF][HEAD_DIM];
    __shared__ float Vs[BKF][HEAD_DIM];
    __shared__ float Ps[BQ][BKF];

    const int bh = blockIdx.y;
    const int b  = bh / N_HEADS;
    const int h  = bh % N_HEADS;
    const int q0 = blockIdx.x * BQ;

    const int tid  = threadIdx.x;
    const int row  = tid >> 2;
    const int part = tid & 3;
    const int qg   = q0 + row;

    const float scale = 0.08838834764831845f;

    float qf[32];
    const float* qp = Q + ((size_t)(b * SEQ + qg)) * D_MODEL + h * HEAD_DIM + part * 32;
#pragma unroll
    for (int i = 0; i < 32; i += 4)
        *(float4*)(qf + i) = *(const float4*)(qp + i);

    float acc[32];
#pragma unroll
    for (int i = 0; i < 32; i++) acc[i] = 0.f;
    float m = -1e30f, l = 0.f;

    const int kend = q0 + BQ;
    for (int k0 = 0; k0 < kend; k0 += BKF) {
        __syncthreads();
        {
            const size_t rbase = (size_t)(b * SEQ + k0) * D_MODEL + h * HEAD_DIM;
            for (int idx = tid; idx < BKF * (HEAD_DIM / 4); idx += 256) {
                int r = idx >> 5;
                int c = (idx & 31) * 4;
                ((float4*)Ks)[idx] = *(const float4*)(K + rbase + (size_t)r * D_MODEL + c);
                ((float4*)Vs)[idx] = *(const float4*)(V + rbase + (size_t)r * D_MODEL + c);
            }
        }
        __syncthreads();

        float sv[BKF / 4];
        float mblk = -1e30f;
#pragma unroll
        for (int j = 0; j < BKF; j++) {
            const float* kr = &Ks[j][part * 32];
            float d = 0.f;
#pragma unroll
            for (int i = 0; i < 32; i++) d = fmaf(qf[i], kr[i], d);
            d += __shfl_xor_sync(0xffffffffu, d, 1);
            d += __shfl_xor_sync(0xffffffffu, d, 2);
            d *= scale;
            int kg = k0 + j;
            d = (kg <= qg) ? d : -1e30f;
            if ((j & 3) == part) sv[j >> 2] = d;
            mblk = fmaxf(mblk, d);
        }

        float mnew  = fmaxf(m, mblk);
        float alpha = __expf(m - mnew);
        float ladd  = 0.f;
#pragma unroll
        for (int jj = 0; jj < BKF / 4; jj++) {
            float p = __expf(sv[jj] - mnew);
            ladd += p;
            Ps[row][jj * 4 + part] = p;
        }
        ladd += __shfl_xor_sync(0xffffffffu, ladd, 1);
        ladd += __shfl_xor_sync(0xffffffffu, ladd, 2);
        l = l * alpha + ladd;
        m = mnew;
#pragma unroll
        for (int i = 0; i < 32; i++) acc[i] *= alpha;
        __syncwarp();

#pragma unroll 4
        for (int j = 0; j < BKF; j++) {
            float p = Ps[row][j];
            const float* vr = &Vs[j][part * 32];
#pragma unroll
            for (int i = 0; i < 32; i++) acc[i] = fmaf(p, vr[i], acc[i]);
        }
    }

    float inv_l = 1.0f / l;
    float* op = O + ((size_t)(b * SEQ + qg)) * D_MODEL + h * HEAD_DIM + part * 32;
#pragma unroll
    for (int i = 0; i < 32; i++) op[i] = acc[i] * inv_l;
}

// ============================================================================
// launch
// ============================================================================
extern "C" void kernel_launch(void* const* d_in, const int* in_sizes, int n_in,
                              void* d_out, int out_size)
{
    const float* x   = (const float*)d_in[0];
    const int*   pos = (const int*)  d_in[1];
    const float* Wq  = (const float*)d_in[2];
    const float* Wk  = (const float*)d_in[3];
    const float* Wv  = (const float*)d_in[4];
    const float* Wo  = (const float*)d_in[5];
    float* out = (float*)d_out;

    float *Qb, *Kb, *Vb, *Cb;
    __nv_bfloat16 *xh, *xl, *ch, *cl, *Wh, *Wl;
    cudaGetSymbolAddress((void**)&Qb, g_Q);
    cudaGetSymbolAddress((void**)&Kb, g_K);
    cudaGetSymbolAddress((void**)&Vb, g_V);
    cudaGetSymbolAddress((void**)&Cb, g_C);
    cudaGetSymbolAddress((void**)&xh, g_xh);
    cudaGetSymbolAddress((void**)&xl, g_xl);
    cudaGetSymbolAddress((void**)&ch, g_ch);
    cudaGetSymbolAddress((void**)&cl, g_cl);
    cudaGetSymbolAddress((void**)&Wh, g_Wh);
    cudaGetSymbolAddress((void**)&Wl, g_Wl);

    cudaFuncSetAttribute(mma_gemm_kernel,
                         cudaFuncAttributeMaxDynamicSharedMemorySize, SMEM_GEMM);

    const size_t WSZ = (size_t)D_MODEL * D_MODEL;
    const int x_n4 = (M_TOT * D_MODEL) / 4;
    const int w_n4 = (int)(WSZ / 4);

    // split conversions
    cvt_kernel<<<(x_n4 + 255) / 256, 256>>>(x, xh, xl, x_n4);
    cvt_kernel<<<(w_n4 + 255) / 256, 256>>>(Wq, Wh + 0 * WSZ, Wl + 0 * WSZ, w_n4);
    cvt_kernel<<<(w_n4 + 255) / 256, 256>>>(Wk, Wh + 1 * WSZ, Wl + 1 * WSZ, w_n4);
    cvt_kernel<<<(w_n4 + 255) / 256, 256>>>(Wv, Wh + 2 * WSZ, Wl + 2 * WSZ, w_n4);
    cvt_kernel<<<(w_n4 + 255) / 256, 256>>>(Wo, Wh + 3 * WSZ, Wl + 3 * WSZ, w_n4);

    // projections on tensor cores (mma.sync)
    dim3 gGrid(D_MODEL / 128, M_TOT / 128);   // (16, 32)
    mma_gemm_kernel<<<gGrid, 256, SMEM_GEMM>>>(xh, xl, Wh + 0 * WSZ, Wl + 0 * WSZ, Qb);
    mma_gemm_kernel<<<gGrid, 256, SMEM_GEMM>>>(xh, xl, Wh + 1 * WSZ, Wl + 1 * WSZ, Kb);
    mma_gemm_kernel<<<gGrid, 256, SMEM_GEMM>>>(xh, xl, Wh + 2 * WSZ, Wl + 2 * WSZ, Vb);

    int ropeTotal = BATCH * SEQ * N_HEADS * (HEAD_DIM / 2);
    rope_kernel<<<(ropeTotal + 255) / 256, 256>>>(Qb, Kb, pos);

    dim3 flashGrid(SEQ / BQ, BATCH * N_HEADS);   // (32, 32)
    flash_kernel<<<flashGrid, 256>>>(Qb, Kb, Vb, Cb);

    // output projection
    cvt_kernel<<<(x_n4 + 255) / 256, 256>>>(Cb, ch, cl, x_n4);
    mma_gemm_kernel<<<gGrid, 256, SMEM_GEMM>>>(ch, cl, Wh + 3 * WSZ, Wl + 3 * WSZ, out);
}

// round 6
// speedup vs baseline: 2.1664x; 1.0669x over previous
#include <cuda_runtime.h>
#include <cuda_bf16.h>
#include <cstdint>
#include <math.h>

// ---------------- problem constants ----------------
#define D_MODEL  2048
#define N_HEADS  16
#define HEAD_DIM 128
#define BATCH    2
#define SEQ      2048
#define M_TOT    (BATCH * SEQ)      // 4096 rows
#define N_QKV    (3 * D_MODEL)      // 6144 fused QKV width

// ---------------- scratch (alloc-free rule: __device__ globals) ----------------
__device__ float g_QKV[M_TOT * N_QKV];     // [token][Q(2048) | K(2048) | V(2048)]
__device__ float g_C[M_TOT * D_MODEL];     // attention context

__device__ __nv_bfloat16 g_xh[M_TOT * D_MODEL];
__device__ __nv_bfloat16 g_xl[M_TOT * D_MODEL];
__device__ __nv_bfloat16 g_ch[M_TOT * D_MODEL];
__device__ __nv_bfloat16 g_cl[M_TOT * D_MODEL];
__device__ __nv_bfloat16 g_Wh[4 * D_MODEL * D_MODEL];   // Wq,Wk,Wv,Wo packed
__device__ __nv_bfloat16 g_Wl[4 * D_MODEL * D_MODEL];

// ============================================================================
// PTX helpers (compute_103-safe: mma.sync / ldmatrix / cp.async only)
// ============================================================================
__device__ __forceinline__ uint32_t smem_u32(const void* p) {
    uint32_t a;
    asm("{ .reg .u64 t; cvta.to.shared.u64 t, %1; cvt.u32.u64 %0, t; }" : "=r"(a) : "l"(p));
    return a;
}
__device__ __forceinline__ void ldmatrix_x4(uint32_t* r, uint32_t addr) {
    asm volatile("ldmatrix.sync.aligned.m8n8.x4.shared.b16 {%0,%1,%2,%3}, [%4];"
                 : "=r"(r[0]), "=r"(r[1]), "=r"(r[2]), "=r"(r[3]) : "r"(addr));
}
__device__ __forceinline__ void mma_bf16(float* c, const uint32_t* a, const uint32_t* b) {
    asm volatile(
        "mma.sync.aligned.m16n8k16.row.col.f32.bf16.bf16.f32 "
        "{%0,%1,%2,%3}, {%4,%5,%6,%7}, {%8,%9}, {%0,%1,%2,%3};"
        : "+f"(c[0]), "+f"(c[1]), "+f"(c[2]), "+f"(c[3])
        : "r"(a[0]), "r"(a[1]), "r"(a[2]), "r"(a[3]), "r"(b[0]), "r"(b[1]));
}
__device__ __forceinline__ void cp16(uint32_t s, const void* g) {
    asm volatile("cp.async.cg.shared.global [%0], [%1], 16;" :: "r"(s), "l"(g));
}
__device__ __forceinline__ void cp_commit() {
    asm volatile("cp.async.commit_group;" ::: "memory");
}
__device__ __forceinline__ void cp_wait2() {
    asm volatile("cp.async.wait_group 2;" ::: "memory");
}

// ============================================================================
// fp32 -> bf16 hi/lo split conversion (vectorized)
// ============================================================================
__global__ void cvt_kernel(const float* __restrict__ in,
                           __nv_bfloat16* __restrict__ hi,
                           __nv_bfloat16* __restrict__ lo, int n4)
{
    int i = blockIdx.x * blockDim.x + threadIdx.x;
    if (i >= n4) return;
    float4 v = ((const float4*)in)[i];
    __nv_bfloat16 h0 = __float2bfloat16(v.x), h1 = __float2bfloat16(v.y);
    __nv_bfloat16 h2 = __float2bfloat16(v.z), h3 = __float2bfloat16(v.w);
    __nv_bfloat16 l0 = __float2bfloat16(v.x - __bfloat162float(h0));
    __nv_bfloat16 l1 = __float2bfloat16(v.y - __bfloat162float(h1));
    __nv_bfloat16 l2 = __float2bfloat16(v.z - __bfloat162float(h2));
    __nv_bfloat16 l3 = __float2bfloat16(v.w - __bfloat162float(h3));
    __nv_bfloat162* hp = (__nv_bfloat162*)hi;
    __nv_bfloat162* lp = (__nv_bfloat162*)lo;
    __nv_bfloat162 a; a.x = h0; a.y = h1; hp[2*i] = a;
    __nv_bfloat162 b; b.x = h2; b.y = h3; hp[2*i+1] = b;
    __nv_bfloat162 c; c.x = l0; c.y = l1; lp[2*i] = c;
    __nv_bfloat162 d; d.x = l2; d.y = l3; lp[2*i+1] = d;
}

// ============================================================================
// bf16x3 GEMM via mma.sync: C[m,n] = sum_k A[m,k]*B[n,k]
// CTA 128(M)x64(N), 128 threads (4 warps, warp tile 64x32).
// BK=32, 3-stage cp.async pipeline (24KB/stage), prefetch issued at loop top.
// 3 CTAs/SM (launch_bounds(128,3)): 12 warps/SM for latency hiding.
// ============================================================================
#define BK        32
#define NITER     (D_MODEL / BK)          // 64
#define OFF_AH    0
#define OFF_AL    8192
#define OFF_BH    16384
#define OFF_BL    20480
#define STAGE_B3  24576                   // 24 KB per stage
#define SMEM_GEMM (3 * STAGE_B3 + 128)    // 72 KB + align pad

__device__ __forceinline__ uint32_t sw_off(int row, int chunk) {
    return (uint32_t)(row * 64 + ((chunk ^ ((row >> 1) & 3)) << 4));
}

__device__ __forceinline__ void issue_stage(
    uint32_t stage,
    const __nv_bfloat16* __restrict__ Ah, const __nv_bfloat16* __restrict__ Al,
    const __nv_bfloat16* __restrict__ Bh, const __nv_bfloat16* __restrict__ Bl,
    int bm, int bn, int k0, int tid)
{
    // A tiles: 128 rows x 4 x 16B chunks (Ah + Al)
#pragma unroll
    for (int j = 0; j < 4; j++) {
        int idx = tid + 128 * j;            // 0..511
        int row = idx >> 2;
        int ch  = idx & 3;
        uint32_t so = sw_off(row, ch);
        size_t ga = (size_t)(bm + row) * D_MODEL + k0 + ch * 8;
        cp16(stage + OFF_AH + so, Ah + ga);
        cp16(stage + OFF_AL + so, Al + ga);
    }
    // B tiles: 64 rows x 4 chunks (Bh + Bl)
#pragma unroll
    for (int j = 0; j < 2; j++) {
        int idx = tid + 128 * j;            // 0..255
        int row = idx >> 2;
        int ch  = idx & 3;
        uint32_t so = sw_off(row, ch);
        size_t gb = (size_t)(bn + row) * D_MODEL + k0 + ch * 8;
        cp16(stage + OFF_BH + so, Bh + gb);
        cp16(stage + OFF_BL + so, Bl + gb);
    }
}

__global__ void __launch_bounds__(128, 3) mma_gemm_kernel(
    const __nv_bfloat16* __restrict__ Ah, const __nv_bfloat16* __restrict__ Al,
    const __nv_bfloat16* __restrict__ Bh, const __nv_bfloat16* __restrict__ Bl,
    float* __restrict__ C, int ldc)
{
    extern __shared__ char sm_raw[];
    const uint32_t sbase = (smem_u32(sm_raw) + 127u) & ~127u;

    const int tid  = threadIdx.x;
    const int lane = tid & 31;
    const int w    = tid >> 5;
    const int wm   = (w & 1) * 64;      // warp m offset (0/64)
    const int wn   = (w >> 1) * 32;     // warp n offset (0/32)
    const int bm   = blockIdx.y * 128;
    const int bn   = blockIdx.x * 64;

    // ldmatrix lane addressing (verified in R5)
    const int g  = lane >> 3;
    const int li = lane & 7;
    const int aRowL = li + ((g & 1) << 3);
    const int aChL  = g >> 1;
    const int bRowL = li + ((g >> 1) << 3);
    const int bChL  = g & 1;

    float acc[4][4][4];
#pragma unroll
    for (int mi = 0; mi < 4; mi++)
#pragma unroll
        for (int ni = 0; ni < 4; ni++)
#pragma unroll
            for (int r = 0; r < 4; r++) acc[mi][ni][r] = 0.f;

    // prologue: stages 0,1
    issue_stage(sbase + 0 * STAGE_B3, Ah, Al, Bh, Bl, bm, bn, 0, tid);
    cp_commit();
    issue_stage(sbase + 1 * STAGE_B3, Ah, Al, Bh, Bl, bm, bn, BK, tid);
    cp_commit();

    int buf = 0;                 // buffer index of iteration c (c % 3)
    int nbuf = 2;                // buffer index for c+2
    for (int c = 0; c < NITER; c++) {
        // prefetch stage c+2 at loop top (buffer was consumed in iter c-1)
        if (c + 2 < NITER)
            issue_stage(sbase + (uint32_t)nbuf * STAGE_B3, Ah, Al, Bh, Bl,
                        bm, bn, (c + 2) * BK, tid);
        cp_commit();
        cp_wait2();               // ensure stage c complete (<=2 groups pending)
        __syncthreads();

        const uint32_t st  = sbase + (uint32_t)buf * STAGE_B3;
        const uint32_t tAh = st + OFF_AH;
        const uint32_t tAl = st + OFF_AL;
        const uint32_t tBh = st + OFF_BH;
        const uint32_t tBl = st + OFF_BL;

#pragma unroll
        for (int ks = 0; ks < 2; ks++) {
            const int aCh = 2 * ks + aChL;
            const int bCh = 2 * ks + bChL;

            uint32_t ah[4][4], bh[4][2], bl[4][2];
#pragma unroll
            for (int mi = 0; mi < 4; mi++)
                ldmatrix_x4(ah[mi], tAh + sw_off(wm + mi * 16 + aRowL, aCh));
#pragma unroll
            for (int p = 0; p < 2; p++) {
                uint32_t t4[4];
                ldmatrix_x4(t4, tBh + sw_off(wn + p * 16 + bRowL, bCh));
                bh[2 * p][0] = t4[0]; bh[2 * p][1] = t4[1];
                bh[2 * p + 1][0] = t4[2]; bh[2 * p + 1][1] = t4[3];
                ldmatrix_x4(t4, tBl + sw_off(wn + p * 16 + bRowL, bCh));
                bl[2 * p][0] = t4[0]; bl[2 * p][1] = t4[1];
                bl[2 * p + 1][0] = t4[2]; bl[2 * p + 1][1] = t4[3];
            }

#pragma unroll
            for (int mi = 0; mi < 4; mi++)
#pragma unroll
                for (int ni = 0; ni < 4; ni++)
                    mma_bf16(acc[mi][ni], ah[mi], bh[ni]);
#pragma unroll
            for (int mi = 0; mi < 4; mi++)
#pragma unroll
                for (int ni = 0; ni < 4; ni++)
                    mma_bf16(acc[mi][ni], ah[mi], bl[ni]);

            uint32_t al[4][4];
#pragma unroll
            for (int mi = 0; mi < 4; mi++)
                ldmatrix_x4(al[mi], tAl + sw_off(wm + mi * 16 + aRowL, aCh));
#pragma unroll
            for (int mi = 0; mi < 4; mi++)
#pragma unroll
                for (int ni = 0; ni < 4; ni++)
                    mma_bf16(acc[mi][ni], al[mi], bh[ni]);
        }
        __syncthreads();          // all warps done with buf before it is refilled

        buf  = (buf == 2)  ? 0 : buf + 1;
        nbuf = (nbuf == 2) ? 0 : nbuf + 1;
    }

    // epilogue: direct float2 stores
    const int gid = lane >> 2;
    const int tig = lane & 3;
#pragma unroll
    for (int mi = 0; mi < 4; mi++) {
#pragma unroll
        for (int ni = 0; ni < 4; ni++) {
            int row = bm + wm + mi * 16 + gid;
            int col = bn + wn + ni * 8 + tig * 2;
            float2 v0 = make_float2(acc[mi][ni][0], acc[mi][ni][1]);
            float2 v1 = make_float2(acc[mi][ni][2], acc[mi][ni][3]);
            *(float2*)(C + (size_t)row * ldc + col) = v0;
            *(float2*)(C + (size_t)(row + 8) * ldc + col) = v1;
        }
    }
}

// ============================================================================
// RoPE in-place on the fused QKV buffer (Q at col 0, K at col 2048; stride 6144)
// ============================================================================
__global__ void rope_kernel(float* __restrict__ QKV, const int* __restrict__ pos)
{
    int idx = blockIdx.x * blockDim.x + threadIdx.x;
    const int total = BATCH * SEQ * N_HEADS * (HEAD_DIM / 2);
    if (idx >= total) return;

    int i  = idx & 63;
    int h  = (idx >> 6) & (N_HEADS - 1);
    int ss = (idx >> 10) & (SEQ - 1);
    int b  = idx >> 21;

    int p = pos[b * SEQ + ss];
    float inv_freq = powf(10000.0f, -(2.0f * (float)i) / 128.0f);
    float ang = (float)p * inv_freq;
    float s, c;
    sincosf(ang, &s, &c);

    size_t base = ((size_t)(b * SEQ + ss)) * N_QKV + h * HEAD_DIM + 2 * i;
    float qe = QKV[base], qo = QKV[base + 1];
    QKV[base]     = qe * c - qo * s;
    QKV[base + 1] = qe * s + qo * c;
    size_t kb = base + D_MODEL;
    float ke = QKV[kb], ko = QKV[kb + 1];
    QKV[kb]     = ke * c - ko * s;
    QKV[kb + 1] = ke * s + ko * c;
}

// ============================================================================
// Causal flash attention, fp32. Q/K/V read from fused buffer (stride 6144),
// O written to g_C (stride 2048).
// ============================================================================
#define BQ 64
#define BKF 32

__global__ __launch_bounds__(256) void flash_kernel(const float* __restrict__ Q,
                                                    const float* __restrict__ K,
                                                    const float* __restrict__ V,
                                                    float* __restrict__ O)
{
    __shared__ float Ks[BKF][HEAD_DIM];
    __shared__ float Vs[BKF][HEAD_DIM];
    __shared__ float Ps[BQ][BKF];

    const int bh = blockIdx.y;
    const int b  = bh / N_HEADS;
    const int h  = bh % N_HEADS;
    const int q0 = blockIdx.x * BQ;

    const int tid  = threadIdx.x;
    const int row  = tid >> 2;
    const int part = tid & 3;
    const int qg   = q0 + row;

    const float scale = 0.08838834764831845f;

    float qf[32];
    const float* qp = Q + ((size_t)(b * SEQ + qg)) * N_QKV + h * HEAD_DIM + part * 32;
#pragma unroll
    for (int i = 0; i < 32; i += 4)
        *(float4*)(qf + i) = *(const float4*)(qp + i);

    float acc[32];
#pragma unroll
    for (int i = 0; i < 32; i++) acc[i] = 0.f;
    float m = -1e30f, l = 0.f;

    const int kend = q0 + BQ;
    for (int k0 = 0; k0 < kend; k0 += BKF) {
        __syncthreads();
        {
            const size_t rbase = (size_t)(b * SEQ + k0) * N_QKV + h * HEAD_DIM;
            for (int idx = tid; idx < BKF * (HEAD_DIM / 4); idx += 256) {
                int r = idx >> 5;
                int c = (idx & 31) * 4;
                ((float4*)Ks)[idx] = *(const float4*)(K + rbase + (size_t)r * N_QKV + c);
                ((float4*)Vs)[idx] = *(const float4*)(V + rbase + (size_t)r * N_QKV + c);
            }
        }
        __syncthreads();

        float sv[BKF / 4];
        float mblk = -1e30f;
#pragma unroll
        for (int j = 0; j < BKF; j++) {
            const float* kr = &Ks[j][part * 32];
            float d = 0.f;
#pragma unroll
            for (int i = 0; i < 32; i++) d = fmaf(qf[i], kr[i], d);
            d += __shfl_xor_sync(0xffffffffu, d, 1);
            d += __shfl_xor_sync(0xffffffffu, d, 2);
            d *= scale;
            int kg = k0 + j;
            d = (kg <= qg) ? d : -1e30f;
            if ((j & 3) == part) sv[j >> 2] = d;
            mblk = fmaxf(mblk, d);
        }

        float mnew  = fmaxf(m, mblk);
        float alpha = __expf(m - mnew);
        float ladd  = 0.f;
#pragma unroll
        for (int jj = 0; jj < BKF / 4; jj++) {
            float p = __expf(sv[jj] - mnew);
            ladd += p;
            Ps[row][jj * 4 + part] = p;
        }
        ladd += __shfl_xor_sync(0xffffffffu, ladd, 1);
        ladd += __shfl_xor_sync(0xffffffffu, ladd, 2);
        l = l * alpha + ladd;
        m = mnew;
#pragma unroll
        for (int i = 0; i < 32; i++) acc[i] *= alpha;
        __syncwarp();

#pragma unroll 4
        for (int j = 0; j < BKF; j++) {
            float p = Ps[row][j];
            const float* vr = &Vs[j][part * 32];
#pragma unroll
            for (int i = 0; i < 32; i++) acc[i] = fmaf(p, vr[i], acc[i]);
        }
    }

    float inv_l = 1.0f / l;
    float* op = O + ((size_t)(b * SEQ + qg)) * D_MODEL + h * HEAD_DIM + part * 32;
#pragma unroll
    for (int i = 0; i < 32; i++) op[i] = acc[i] * inv_l;
}

// ============================================================================
// launch
// ============================================================================
extern "C" void kernel_launch(void* const* d_in, const int* in_sizes, int n_in,
                              void* d_out, int out_size)
{
    const float* x   = (const float*)d_in[0];
    const int*   pos = (const int*)  d_in[1];
    const float* Wq  = (const float*)d_in[2];
    const float* Wk  = (const float*)d_in[3];
    const float* Wv  = (const float*)d_in[4];
    const float* Wo  = (const float*)d_in[5];
    float* out = (float*)d_out;

    float *QKVb, *Cb;
    __nv_bfloat16 *xh, *xl, *ch, *cl, *Wh, *Wl;
    cudaGetSymbolAddress((void**)&QKVb, g_QKV);
    cudaGetSymbolAddress((void**)&Cb, g_C);
    cudaGetSymbolAddress((void**)&xh, g_xh);
    cudaGetSymbolAddress((void**)&xl, g_xl);
    cudaGetSymbolAddress((void**)&ch, g_ch);
    cudaGetSymbolAddress((void**)&cl, g_cl);
    cudaGetSymbolAddress((void**)&Wh, g_Wh);
    cudaGetSymbolAddress((void**)&Wl, g_Wl);

    cudaFuncSetAttribute(mma_gemm_kernel,
                         cudaFuncAttributeMaxDynamicSharedMemorySize, SMEM_GEMM);

    const size_t WSZ = (size_t)D_MODEL * D_MODEL;
    const int x_n4 = (M_TOT * D_MODEL) / 4;
    const int w_n4 = (int)(WSZ / 4);

    // split conversions
    cvt_kernel<<<(x_n4 + 255) / 256, 256>>>(x, xh, xl, x_n4);
    cvt_kernel<<<(w_n4 + 255) / 256, 256>>>(Wq, Wh + 0 * WSZ, Wl + 0 * WSZ, w_n4);
    cvt_kernel<<<(w_n4 + 255) / 256, 256>>>(Wk, Wh + 1 * WSZ, Wl + 1 * WSZ, w_n4);
    cvt_kernel<<<(w_n4 + 255) / 256, 256>>>(Wv, Wh + 2 * WSZ, Wl + 2 * WSZ, w_n4);
    cvt_kernel<<<(w_n4 + 255) / 256, 256>>>(Wo, Wh + 3 * WSZ, Wl + 3 * WSZ, w_n4);

    // fused QKV projection: B rows 0..6143 = [Wq;Wk;Wv]
    dim3 qkvGrid(N_QKV / 64, M_TOT / 128);     // (96, 32)
    mma_gemm_kernel<<<qkvGrid, 128, SMEM_GEMM>>>(xh, xl, Wh, Wl, QKVb, N_QKV);

    int ropeTotal = BATCH * SEQ * N_HEADS * (HEAD_DIM / 2);
    rope_kernel<<<(ropeTotal + 255) / 256, 256>>>(QKVb, pos);

    dim3 flashGrid(SEQ / BQ, BATCH * N_HEADS);   // (32, 32)
    flash_kernel<<<flashGrid, 256>>>(QKVb, QKVb + D_MODEL, QKVb + 2 * D_MODEL, Cb);

    // output projection
    cvt_kernel<<<(x_n4 + 255) / 256, 256>>>(Cb, ch, cl, x_n4);
    dim3 oGrid(D_MODEL / 64, M_TOT / 128);       // (32, 32)
    mma_gemm_kernel<<<oGrid, 128, SMEM_GEMM>>>(ch, cl, Wh + 3 * WSZ, Wl + 3 * WSZ, out, D_MODEL);
}